// round 17
// baseline (speedup 1.0000x reference)
#include <cuda_runtime.h>
#include <cuda_bf16.h>
#include <cstdint>
#include <cstddef>

// Problem constants
#define B_   8
#define S_   1024
#define D_   1024
#define H_   16
#define HD_  64
#define OD_  3072
#define ROWS_ (B_ * S_)             // 8192
#define BHSZ_ (B_ * H_ * S_ * HD_) // 8,388,608

#define NEG_BIG (-3.0e38f)

// Scratch (device globals, no allocation)
__device__ float g_lo[ROWS_ * 4];
__device__ __nv_bfloat16 g_Ah[ROWS_ * D_];
__device__ __nv_bfloat16 g_Al[ROWS_ * D_];
__device__ __nv_bfloat16 g_Bh[OD_ * D_];
__device__ __nv_bfloat16 g_Bl[OD_ * D_];
// Q/K/V in bf16 split (hi,lo) pairs, layout [b*H+h][s][d]
__device__ __nv_bfloat16 g_Qh[BHSZ_], g_Ql[BHSZ_];
__device__ __nv_bfloat16 g_Kh[BHSZ_], g_Kl[BHSZ_];
__device__ __nv_bfloat16 g_Vh[BHSZ_], g_Vl[BHSZ_];

// ---------------------------------------------------------------------------
// Helpers (sm_80-level features only: cp.async, ldmatrix, mma.sync)
// ---------------------------------------------------------------------------
__device__ __forceinline__ uint32_t smem_u32(const void* p) {
    return (uint32_t)__cvta_generic_to_shared(p);
}
__device__ __forceinline__ void cp16(uint32_t dst, const void* src) {
    asm volatile("cp.async.cg.shared.global [%0], [%1], 16;" :: "r"(dst), "l"(src));
}
__device__ __forceinline__ void ldsm4(uint32_t* r, uint32_t addr) {
    asm volatile("ldmatrix.sync.aligned.m8n8.x4.shared.b16 {%0,%1,%2,%3}, [%4];"
                 : "=r"(r[0]), "=r"(r[1]), "=r"(r[2]), "=r"(r[3]) : "r"(addr));
}
__device__ __forceinline__ void ldsm4t(uint32_t* r, uint32_t addr) {
    asm volatile("ldmatrix.sync.aligned.m8n8.x4.trans.shared.b16 {%0,%1,%2,%3}, [%4];"
                 : "=r"(r[0]), "=r"(r[1]), "=r"(r[2]), "=r"(r[3]) : "r"(addr));
}
__device__ __forceinline__ void mma16816(float* c, const uint32_t* a,
                                         uint32_t b0, uint32_t b1) {
    asm volatile(
        "mma.sync.aligned.m16n8k16.row.col.f32.bf16.bf16.f32 "
        "{%0,%1,%2,%3}, {%4,%5,%6,%7}, {%8,%9}, {%0,%1,%2,%3};"
        : "+f"(c[0]), "+f"(c[1]), "+f"(c[2]), "+f"(c[3])
        : "r"(a[0]), "r"(a[1]), "r"(a[2]), "r"(a[3]), "r"(b0), "r"(b1));
}
__device__ __forceinline__ float dot4(float4 a, float4 b) {
    return a.x * b.x + a.y * b.y + a.z * b.z + a.w * b.w;
}
// Swizzled byte offset of 16B chunk (r, cc in [0,4)) in a tile with 64B rows.
__device__ __forceinline__ uint32_t swz(int r, int cc) {
    return (uint32_t)(r * 64 + ((cc ^ ((r >> 1) & 3)) << 4));
}
// Swizzled byte offset of 16B chunk (r, c in [0,8)) in a tile with 128B rows.
__device__ __forceinline__ uint32_t off128(int r, int c) {
    return (uint32_t)(r * 128 + (((c ^ r) & 7) << 4));
}
// Store fp32 pair as bf16 (hi,lo) split pairs.
__device__ __forceinline__ void store_hl(__nv_bfloat16* dh, __nv_bfloat16* dl,
                                         size_t off, float2 v) {
    __nv_bfloat162 h, l;
    h.x = __float2bfloat16_rn(v.x); h.y = __float2bfloat16_rn(v.y);
    l.x = __float2bfloat16_rn(v.x - __bfloat162float(h.x));
    l.y = __float2bfloat16_rn(v.y - __bfloat162float(h.y));
    *(__nv_bfloat162*)(dh + off) = h;
    *(__nv_bfloat162*)(dl + off) = l;
}

// ---------------------------------------------------------------------------
// splitB: W = hi + lo (each bf16)
// ---------------------------------------------------------------------------
__global__ __launch_bounds__(256) void splitB_kernel(const float* __restrict__ src) {
    int i = blockIdx.x * 256 + threadIdx.x;
    float x = src[i];
    __nv_bfloat16 h = __float2bfloat16_rn(x);
    g_Bh[i] = h;
    g_Bl[i] = __float2bfloat16_rn(x - __bfloat162float(h));
}

// ---------------------------------------------------------------------------
// Kernel 1 (fused): per row — LoRA lo projection AND bf16 split of hidden.
// ---------------------------------------------------------------------------
__global__ __launch_bounds__(128) void lo_split_kernel(const float* __restrict__ Hs,
                                                       const float* __restrict__ lA,
                                                       const int*   __restrict__ am) {
    const int row = blockIdx.x;
    const int b   = row >> 10;
    const int a   = am[b];
    const float* hr = Hs + (size_t)row * D_;
    const float* A  = lA + (size_t)a * 4 * D_;

    float p0 = 0.f, p1 = 0.f, p2 = 0.f, p3 = 0.f;
    for (int d = threadIdx.x; d < D_; d += 128) {
        float hv = hr[d];
        __nv_bfloat16 h = __float2bfloat16_rn(hv);
        g_Ah[(size_t)row * D_ + d] = h;
        g_Al[(size_t)row * D_ + d] = __float2bfloat16_rn(hv - __bfloat162float(h));
        p0 += hv * A[d];
        p1 += hv * A[D_ + d];
        p2 += hv * A[2 * D_ + d];
        p3 += hv * A[3 * D_ + d];
    }
    __shared__ float red[4][128];
    red[0][threadIdx.x] = p0;
    red[1][threadIdx.x] = p1;
    red[2][threadIdx.x] = p2;
    red[3][threadIdx.x] = p3;
    __syncthreads();
    for (int off = 64; off > 0; off >>= 1) {
        if (threadIdx.x < off) {
            red[0][threadIdx.x] += red[0][threadIdx.x + off];
            red[1][threadIdx.x] += red[1][threadIdx.x + off];
            red[2][threadIdx.x] += red[2][threadIdx.x + off];
            red[3][threadIdx.x] += red[3][threadIdx.x + off];
        }
        __syncthreads();
    }
    if (threadIdx.x < 4)
        g_lo[row * 4 + threadIdx.x] = red[threadIdx.x][0];
}

// ---------------------------------------------------------------------------
// Kernel 2: QKV GEMM via warp-level mma.sync (bf16 split: ah*bh+al*bh+ah*bl).
// CTA 64x192, BK=32, 192 threads = 6 warps (2M x 3N), warp tile 32x64.
// Warp N = 64 = exactly one head -> in-register RoPE preserved.
// Grid 128x16 = 2048 CTAs at 2/SM -> 6.92 waves (tail 1.2% vs 13% before).
// 3-stage cp.async pipeline, one __syncthreads per K-chunk.
// ---------------------------------------------------------------------------
#define ATILEB 4096                      // 64 rows x 64B, per h/l array
#define BTILEB 12288                     // 192 rows x 64B, per h/l array
#define BUFB   (2 * ATILEB + 2 * BTILEB) // 32768
#define QKV_SMEM (3 * BUFB)              // 98304

__global__ __launch_bounds__(192, 2) void qkv_mma_kernel(
    const float* __restrict__ bias, const float* __restrict__ lB,
    const int* __restrict__ am,
    const float* __restrict__ cosp, const float* __restrict__ sinp) {

    extern __shared__ __align__(1024) char dyn[];
    const uint32_t sbase = smem_u32(dyn);

    __shared__ float  s_bias[192];
    __shared__ float4 s_lB[192];

    const int t    = threadIdx.x;
    const int lane = t & 31, wid = t >> 5;       // wid 0..5
    const int wM = (wid >= 3) ? 1 : 0;
    const int wN = wid - 3 * wM;                 // 0..2
    const int rowBase = blockIdx.y * 64;
    const int colBase = blockIdx.x * 192;

    const __nv_bfloat16* gAh = g_Ah + (size_t)rowBase * D_;
    const __nv_bfloat16* gAl = g_Al + (size_t)rowBase * D_;
    const __nv_bfloat16* gBh = g_Bh + (size_t)colBase * D_;
    const __nv_bfloat16* gBl = g_Bl + (size_t)colBase * D_;

    auto load_chunk = [&](int kk, int bi) {
        uint32_t base = sbase + bi * BUFB;
        int gcolb = kk * 32;
        // A: 2 arrays x 256 chunks (64 rows x 4 cc)
        for (int idx = t; idx < 512; idx += 192) {
            int arr = idx >> 8;
            int id  = idx & 255;
            int r = id >> 2, cc = id & 3;
            size_t go = (size_t)r * D_ + gcolb + cc * 8;
            cp16(base + arr * ATILEB + swz(r, cc), (arr ? gAl : gAh) + go);
        }
        // B: 2 arrays x 768 chunks (192 rows x 4 cc)
        for (int idx = t; idx < 1536; idx += 192) {
            int arr = (idx >= 768) ? 1 : 0;
            int id  = idx - arr * 768;
            int r = id >> 2, cc = id & 3;
            size_t go = (size_t)r * D_ + gcolb + cc * 8;
            cp16(base + 2 * ATILEB + arr * BTILEB + swz(r, cc), (arr ? gBl : gBh) + go);
        }
        asm volatile("cp.async.commit_group;");
    };

    float acc[2][8][4];
#pragma unroll
    for (int mi = 0; mi < 2; mi++)
#pragma unroll
        for (int nj = 0; nj < 8; nj++)
#pragma unroll
            for (int e = 0; e < 4; e++) acc[mi][nj][e] = 0.f;

    load_chunk(0, 0);
    load_chunk(1, 1);

    int cur = 0, nxt2 = 2;
    for (int kk = 0; kk < 32; kk++) {
        if (kk < 31)
            asm volatile("cp.async.wait_group 1;" ::: "memory");
        else
            asm volatile("cp.async.wait_group 0;" ::: "memory");
        __syncthreads();  // chunk kk visible AND all warps done with chunk kk-1

        if (kk < 30) load_chunk(kk + 2, nxt2);  // overwrites buffer of kk-1

        const uint32_t base = sbase + cur * BUFB;
#pragma unroll
        for (int ks = 0; ks < 2; ks++) {
            uint32_t ah[2][4], al[2][4];
            const int arow = wM * 32 + (lane & 15);
            const int acc_c = ks * 2 + (lane >> 4);
#pragma unroll
            for (int mi = 0; mi < 2; mi++) {
                uint32_t off = swz(arow + mi * 16, acc_c);
                ldsm4(ah[mi], base + off);
                ldsm4(al[mi], base + ATILEB + off);
            }
            const int nrow0 = wN * 64 + ((lane >> 4) << 3) + (lane & 7);
            const int bcc   = ks * 2 + ((lane >> 3) & 1);
#pragma unroll
            for (int p = 0; p < 4; p++) {
                uint32_t off = swz(nrow0 + p * 16, bcc);
                uint32_t bh4[4], bl4[4];
                ldsm4(bh4, base + 2 * ATILEB + off);
                ldsm4(bl4, base + 2 * ATILEB + BTILEB + off);
#pragma unroll
                for (int sub = 0; sub < 2; sub++) {
                    const int nj = 2 * p + sub;
#pragma unroll
                    for (int mi = 0; mi < 2; mi++) {
                        mma16816(acc[mi][nj], ah[mi], bh4[2 * sub], bh4[2 * sub + 1]);
                        mma16816(acc[mi][nj], al[mi], bh4[2 * sub], bh4[2 * sub + 1]);
                        mma16816(acc[mi][nj], ah[mi], bl4[2 * sub], bl4[2 * sub + 1]);
                    }
                }
            }
        }
        cur  = (cur  == 2) ? 0 : cur + 1;
        nxt2 = (nxt2 == 2) ? 0 : nxt2 + 1;
    }

    // ---------------- Epilogue ----------------
    const int b     = rowBase >> 10;
    const int a     = am[b];
    const int wcol  = colBase + wN * 64;     // head-aligned (multiple of 64)
    const int part  = wcol >> 10;            // 0=Q, 1=K, 2=V
    const int h     = (wcol & 1023) >> 6;

    __nv_bfloat16* dh = (part == 0) ? g_Qh : (part == 1) ? g_Kh : g_Vh;
    __nv_bfloat16* dl = (part == 0) ? g_Ql : (part == 1) ? g_Kl : g_Vl;

    {
        int o = colBase + t;
        s_bias[t] = bias[o];
        s_lB[t]   = *(const float4*)(lB + ((size_t)a * OD_ + o) * 4);
    }
    __syncthreads();

    const int g   = lane >> 2;
    const int tig = lane & 3;

#pragma unroll
    for (int mi = 0; mi < 2; mi++) {
#pragma unroll
        for (int hh = 0; hh < 2; hh++) {
            const int row = rowBase + wM * 32 + mi * 16 + hh * 8 + g;
            const int s   = row & 1023;
            const float4 lov = *(const float4*)(g_lo + row * 4);
            const size_t rowoff = ((size_t)(b * H_ + h) * S_ + s) * HD_;

            if (part < 2) {
                const float* cr = cosp + (size_t)row * HD_;
                const float* sr = sinp + (size_t)row * HD_;
#pragma unroll
                for (int nj = 0; nj < 4; nj++) {
                    const int c  = nj * 8 + tig * 2;     // < 32
                    const int cl = wN * 64 + c;
                    float v0 = acc[mi][nj][hh * 2 + 0]     + s_bias[cl]      + 0.25f * dot4(lov, s_lB[cl]);
                    float v1 = acc[mi][nj][hh * 2 + 1]     + s_bias[cl + 1]  + 0.25f * dot4(lov, s_lB[cl + 1]);
                    float u0 = acc[mi][nj + 4][hh * 2 + 0] + s_bias[cl + 32] + 0.25f * dot4(lov, s_lB[cl + 32]);
                    float u1 = acc[mi][nj + 4][hh * 2 + 1] + s_bias[cl + 33] + 0.25f * dot4(lov, s_lB[cl + 33]);
                    float2 clo = *(const float2*)(cr + c),      slo = *(const float2*)(sr + c);
                    float2 chi = *(const float2*)(cr + c + 32), shi = *(const float2*)(sr + c + 32);
                    store_hl(dh, dl, rowoff + c,
                             make_float2(v0 * clo.x - u0 * slo.x, v1 * clo.y - u1 * slo.y));
                    store_hl(dh, dl, rowoff + c + 32,
                             make_float2(u0 * chi.x + v0 * shi.x, u1 * chi.y + v1 * shi.y));
                }
            } else {
#pragma unroll
                for (int nj = 0; nj < 8; nj++) {
                    const int c  = nj * 8 + tig * 2;
                    const int cl = wN * 64 + c;
                    float v0 = acc[mi][nj][hh * 2 + 0] + s_bias[cl]     + 0.25f * dot4(lov, s_lB[cl]);
                    float v1 = acc[mi][nj][hh * 2 + 1] + s_bias[cl + 1] + 0.25f * dot4(lov, s_lB[cl + 1]);
                    store_hl(dh, dl, rowoff + c, make_float2(v0, v1));
                }
            }
        }
    }
}

// ---------------------------------------------------------------------------
// Kernel 3: flash attention via mma.sync (bf16 splits everywhere).
// CTA = 64 queries x (b,h); 128 threads = 4 warps x 16 query rows.
// ONE barrier per K-tile (wait -> sync -> issue next load -> compute).
// S-GEMM nb-outer so mask+max overlaps subsequent MMA blocks.
// smem = 2 x 33024 = 66048B -> 3 CTAs/SM.
// ---------------------------------------------------------------------------
#define ATT_BSTR 33024
#define ATT_SMEM (2 * ATT_BSTR)  // 66048

__global__ __launch_bounds__(128) void attn_mma_kernel(const float* __restrict__ mask,
                                                       float* __restrict__ out) {
    extern __shared__ __align__(1024) char adyn[];
    const uint32_t sb = smem_u32(adyn);
    const int t = threadIdx.x, lane = t & 31, w = t >> 5;
    const int g = lane >> 2, tig = lane & 3;
    const int bh = blockIdx.y, b = bh >> 4, h = bh & 15;
    const int qt = blockIdx.x;
    const int qbase = w * 16;

    const __nv_bfloat16* gQh = g_Qh + (size_t)bh * S_ * HD_;
    const __nv_bfloat16* gQl = g_Ql + (size_t)bh * S_ * HD_;
    const __nv_bfloat16* gKh = g_Kh + (size_t)bh * S_ * HD_;
    const __nv_bfloat16* gKl = g_Kl + (size_t)bh * S_ * HD_;
    const __nv_bfloat16* gVh = g_Vh + (size_t)bh * S_ * HD_;
    const __nv_bfloat16* gVl = g_Vl + (size_t)bh * S_ * HD_;
    const float* maskb = mask + b * S_;

    auto load_tile = [&](int kt2, int bi) {
        uint32_t base = sb + bi * ATT_BSTR;
#pragma unroll
        for (int i = 0; i < 4; i++) {
            int idx = i * 128 + t;
            int r = idx >> 3, c = idx & 7;
            uint32_t off = off128(r, c);
            size_t so = (size_t)(kt2 * 64 + r) * HD_ + c * 8;
            cp16(base + off,         gKh + so);
            cp16(base + 8192 + off,  gKl + so);
            cp16(base + 16384 + off, gVh + so);
            cp16(base + 24576 + off, gVl + so);
        }
        if (t < 16) cp16(base + 32768 + t * 16, maskb + kt2 * 64 + t * 4);
        asm volatile("cp.async.commit_group;");
    };

    load_tile(0, 0);

    // Q A-fragments loaded directly from global (m16n8k16 A layout).
    uint32_t qh[4][4], ql[4][4];
    {
        const size_t r0 = (size_t)(qt * 64 + qbase + g) * HD_;
        const size_t r1 = (size_t)(qt * 64 + qbase + g + 8) * HD_;
#pragma unroll
        for (int kc = 0; kc < 4; kc++) {
            const int c = 16 * kc + 2 * tig;
            qh[kc][0] = *(const uint32_t*)(gQh + r0 + c);
            qh[kc][1] = *(const uint32_t*)(gQh + r1 + c);
            qh[kc][2] = *(const uint32_t*)(gQh + r0 + c + 8);
            qh[kc][3] = *(const uint32_t*)(gQh + r1 + c + 8);
            ql[kc][0] = *(const uint32_t*)(gQl + r0 + c);
            ql[kc][1] = *(const uint32_t*)(gQl + r1 + c);
            ql[kc][2] = *(const uint32_t*)(gQl + r0 + c + 8);
            ql[kc][3] = *(const uint32_t*)(gQl + r1 + c + 8);
        }
    }

    float m0 = NEG_BIG, m1 = NEG_BIG, l0 = 0.f, l1 = 0.f;
    float o[8][4];
#pragma unroll
    for (int j = 0; j < 8; j++)
#pragma unroll
        for (int e = 0; e < 4; e++) o[j][e] = 0.f;

    for (int kt = 0; kt < 16; kt++) {
        asm volatile("cp.async.wait_group 0;" ::: "memory");
        __syncthreads();  // tile kt visible AND all warps done with tile kt-1

        if (kt < 15) load_tile(kt + 1, (kt + 1) & 1);  // overwrites buffer of kt-1

        const uint32_t base = sb + (kt & 1) * ATT_BSTR;
        const float* mk = (const float*)(adyn + (kt & 1) * ATT_BSTR + 32768);

        // ---- S = Q K^T (3-term split), nb-outer; mask+max per block ----
        float sc[8][4];
        float mt0 = NEG_BIG, mt1 = NEG_BIG;
        const int krow = ((lane >> 4) << 3) + (lane & 7);
#pragma unroll
        for (int nb = 0; nb < 4; nb++) {
#pragma unroll
            for (int sub = 0; sub < 2; sub++)
#pragma unroll
                for (int e = 0; e < 4; e++) sc[2 * nb + sub][e] = 0.f;
#pragma unroll
            for (int kc = 0; kc < 4; kc++) {
                const int kchk = 2 * kc + ((lane >> 3) & 1);
                uint32_t off = off128(nb * 16 + krow, kchk);
                uint32_t kh4[4], kl4[4];
                ldsm4(kh4, base + off);
                ldsm4(kl4, base + 8192 + off);
#pragma unroll
                for (int sub = 0; sub < 2; sub++) {
                    int j = 2 * nb + sub;
                    mma16816(sc[j], qh[kc], kh4[2 * sub], kh4[2 * sub + 1]);
                    mma16816(sc[j], ql[kc], kh4[2 * sub], kh4[2 * sub + 1]);
                    mma16816(sc[j], qh[kc], kl4[2 * sub], kl4[2 * sub + 1]);
                }
            }
#pragma unroll
            for (int sub = 0; sub < 2; sub++) {
                int j = 2 * nb + sub;
                float mk0 = mk[8 * j + 2 * tig], mk1 = mk[8 * j + 2 * tig + 1];
                sc[j][0] = sc[j][0] * 0.125f + mk0;
                sc[j][1] = sc[j][1] * 0.125f + mk1;
                sc[j][2] = sc[j][2] * 0.125f + mk0;
                sc[j][3] = sc[j][3] * 0.125f + mk1;
                mt0 = fmaxf(mt0, fmaxf(sc[j][0], sc[j][1]));
                mt1 = fmaxf(mt1, fmaxf(sc[j][2], sc[j][3]));
            }
        }
        mt0 = fmaxf(mt0, __shfl_xor_sync(0xffffffffu, mt0, 1));
        mt0 = fmaxf(mt0, __shfl_xor_sync(0xffffffffu, mt0, 2));
        mt1 = fmaxf(mt1, __shfl_xor_sync(0xffffffffu, mt1, 1));
        mt1 = fmaxf(mt1, __shfl_xor_sync(0xffffffffu, mt1, 2));

        float mn0 = fmaxf(m0, mt0), mn1 = fmaxf(m1, mt1);
        float a0 = __expf(m0 - mn0), a1 = __expf(m1 - mn1);
        m0 = mn0; m1 = mn1;

        float ls0 = 0.f, ls1 = 0.f;
#pragma unroll
        for (int j = 0; j < 8; j++) {
            sc[j][0] = __expf(sc[j][0] - mn0);
            sc[j][1] = __expf(sc[j][1] - mn0);
            sc[j][2] = __expf(sc[j][2] - mn1);
            sc[j][3] = __expf(sc[j][3] - mn1);
            ls0 += sc[j][0] + sc[j][1];
            ls1 += sc[j][2] + sc[j][3];
        }
        ls0 += __shfl_xor_sync(0xffffffffu, ls0, 1);
        ls0 += __shfl_xor_sync(0xffffffffu, ls0, 2);
        ls1 += __shfl_xor_sync(0xffffffffu, ls1, 1);
        ls1 += __shfl_xor_sync(0xffffffffu, ls1, 2);
        l0 = l0 * a0 + ls0;
        l1 = l1 * a1 + ls1;

#pragma unroll
        for (int j = 0; j < 8; j++) {
            o[j][0] *= a0; o[j][1] *= a0;
            o[j][2] *= a1; o[j][3] *= a1;
        }

        // ---- O += P V (P split in-register; V via ldmatrix.trans) ----
#pragma unroll
        for (int kc = 0; kc < 4; kc++) {
            uint32_t pah[4], pal[4];
#pragma unroll
            for (int q = 0; q < 4; q++) {
                int j = 2 * kc + (q >> 1), e = (q & 1) * 2;
                float p0 = sc[j][e], p1 = sc[j][e + 1];
                __nv_bfloat162 hh, llp;
                hh.x  = __float2bfloat16_rn(p0);
                hh.y  = __float2bfloat16_rn(p1);
                llp.x = __float2bfloat16_rn(p0 - __bfloat162float(hh.x));
                llp.y = __float2bfloat16_rn(p1 - __bfloat162float(hh.y));
                pah[q] = *(uint32_t*)&hh;
                pal[q] = *(uint32_t*)&llp;
            }
            const int vrow = 16 * kc + ((lane >> 3) & 1) * 8 + (lane & 7);
            const int vch0 = (lane >> 4);
#pragma unroll
            for (int ng = 0; ng < 4; ng++) {
                uint32_t off = off128(vrow, 2 * ng + vch0);
                uint32_t vh4[4], vl4[4];
                ldsm4t(vh4, base + 16384 + off);
                ldsm4t(vl4, base + 24576 + off);
#pragma unroll
                for (int sub = 0; sub < 2; sub++) {
                    int nb2 = 2 * ng + sub;
                    mma16816(o[nb2], pah, vh4[2 * sub], vh4[2 * sub + 1]);
                    mma16816(o[nb2], pal, vh4[2 * sub], vh4[2 * sub + 1]);
                    mma16816(o[nb2], pah, vl4[2 * sub], vl4[2 * sub + 1]);
                }
            }
        }
        // no trailing barrier: next iteration's top barrier covers buffer reuse
    }

    // ---- normalize + write out[b, s, h*64 + col] ----
    float inv0 = 1.f / l0, inv1 = 1.f / l1;
    float* ob = out + ((size_t)b * S_ + qt * 64 + qbase + g) * D_ + h * HD_;
#pragma unroll
    for (int nb2 = 0; nb2 < 8; nb2++) {
        int col = 8 * nb2 + 2 * tig;
        *(float2*)(ob + col)          = make_float2(o[nb2][0] * inv0, o[nb2][1] * inv0);
        *(float2*)(ob + 8 * D_ + col) = make_float2(o[nb2][2] * inv1, o[nb2][3] * inv1);
    }
}

// ---------------------------------------------------------------------------
// Launch
// ---------------------------------------------------------------------------
extern "C" void kernel_launch(void* const* d_in, const int* in_sizes, int n_in,
                              void* d_out, int out_size) {
    (void)in_sizes; (void)n_in; (void)out_size;
    const float* Hs   = (const float*)d_in[0];
    const float* mask = (const float*)d_in[1];
    const float* cosp = (const float*)d_in[2];
    const float* sinp = (const float*)d_in[3];
    const int*   am   = (const int*)d_in[4];
    const float* W    = (const float*)d_in[5];
    const float* bias = (const float*)d_in[6];
    const float* lA   = (const float*)d_in[7];
    const float* lB   = (const float*)d_in[8];
    float* out = (float*)d_out;

    cudaFuncSetAttribute(qkv_mma_kernel, cudaFuncAttributeMaxDynamicSharedMemorySize, QKV_SMEM);
    cudaFuncSetAttribute(attn_mma_kernel, cudaFuncAttributeMaxDynamicSharedMemorySize, ATT_SMEM);

    splitB_kernel<<<(OD_ * D_) / 256, 256>>>(W);
    lo_split_kernel<<<ROWS_, 128>>>(Hs, lA, am);
    qkv_mma_kernel<<<dim3(OD_ / 192, ROWS_ / 64), 192, QKV_SMEM>>>(bias, lB, am, cosp, sinp);
    attn_mma_kernel<<<dim3(S_ / 64, B_ * H_), 128, ATT_SMEM>>>(mask, out);
}